// round 11
// baseline (speedup 1.0000x reference)
#include <cuda_runtime.h>
#include <math.h>

// ---------------------------------------------------------------------------
// PrettyPCF, R10 (resubmit after infra failure) = R8 + occupancy (JSPLIT=4)
// + rcp-for-div + scaled coords.
//  * Warp owns one i-point and a 384-long j-slice; 768 blocks all resident.
//  * Coordinates pre-scaled by 1/RMAX: distance test in u-units, cut2 const.
//  * All f32 divisions replaced by rcp.approx (MUFU).
//  * Phase A: ballot + popc-prefix compact survivors' u into warp-private
//    smem queue. Phase B: counted branchless drain, 2-way unroll,
//    exp(-16(zb-u)^2) = ex2(c0[lane] + c1[lane]*u + c2*u^2).
//  * Weights in registers via polynomial acos/atan2 (no libm, no divergence).
// ---------------------------------------------------------------------------

#define NPTS   1536
#define NBINS  50
#define WPB    8                   // warps (== i-points) per block
#define NTHR   (WPB * 32)          // 256
#define ITILES (NPTS / WPB)        // 192
#define JSPLIT 4
#define JLEN   (NPTS / JSPLIT)     // 384
#define JITERS (JLEN / 32)         // 12
#define NBLK   (ITILES * JSPLIT)   // 768
#define QW     JLEN                // per-warp queue capacity (worst case)
#define ZC     1.2f

#define RMAX_D (2.0 * sqrt(1.0 / (2.0 * sqrt(3.0) * 1536.0)))

__device__ float g_acc[NBINS];   // zero-init at load; reset by last block
__device__ int   g_done;

__device__ __forceinline__ float ex2_fast(float x) {
    float y;
    asm("ex2.approx.ftz.f32 %0, %1;" : "=f"(y) : "f"(x));
    return y;
}
__device__ __forceinline__ float rcp_fast(float x) {
    float y;
    asm("rcp.approx.ftz.f32 %0, %1;" : "=f"(y) : "f"(x));
    return y;
}

// acos(x), x in [0,1]; abs err < 6.7e-5 (A&S 4.4.45). acos(1) = 0 exactly.
__device__ __forceinline__ float acos_poly(float x) {
    float p = fmaf(x, fmaf(x, fmaf(x, -0.0187293f, 0.0742610f),
                               -0.2121144f), 1.5707288f);
    return sqrtf(1.0f - x) * p;
}

// atan(r), r in [0,1]; minimax odd poly, abs err ~1e-6.
__device__ __forceinline__ float atan_poly(float r) {
    float r2 = r * r;
    float p = fmaf(r2, fmaf(r2, fmaf(r2, fmaf(r2, fmaf(r2,
              -0.0117212f, 0.05265332f), -0.11643287f),
               0.19354346f), -0.33262347f), 0.99997726f);
    return r * p;
}

// atan2(y, x) for x,y >= 0 (first quadrant), branchless, rcp-based.
__device__ __forceinline__ float atan2_q1(float y, float x) {
    float mn = fminf(x, y);
    float mx = fmaxf(x, y);
    float r  = mn * rcp_fast(fmaxf(mx, 1e-20f));
    float a  = atan_poly(r);
    return (y > x) ? (1.5707963268f - a) : a;
}

__global__ __launch_bounds__(NTHR)
void pcf_kernel(const float* __restrict__ A, const float* __restrict__ B,
                const int* __restrict__ scp, float* __restrict__ out)
{
    __shared__ float sbx[JLEN];          // B x, pre-scaled by 1/RMAX
    __shared__ float sby[JLEN];          // B y, pre-scaled
    __shared__ float swq[WPB * QW];      // per-warp survivor u's
    __shared__ float sacc[NBINS];
    __shared__ int   is_last;

    const int tid   = threadIdx.x;
    const int lane  = tid & 31;
    const int wid   = tid >> 5;
    const int itile = blockIdx.x % ITILES;
    const int jsp   = blockIdx.x / ITILES;
    const int i0    = itile * WPB;
    const int j0    = jsp * JLEN;
    const int i     = i0 + wid;          // this warp's i-point
    float* wq = &swq[wid * QW];

    const float invR = (float)(1.0 / RMAX_D);

    // ---- Stage this block's B slice (scaled to u-units) ----
    for (int t = tid; t < JLEN; t += NTHR) {
        sbx[t] = B[3 * (j0 + t)]     * invR;
        sby[t] = B[3 * (j0 + t) + 1] * invR;
    }
    if (tid < NBINS) sacc[tid] = 0.0f;

    // ---- This warp's i coords ----
    const float ax = A[3 * i];
    const float ay = A[3 * i + 1];
    const float axs = ax * invR;
    const float ays = ay * invR;

    // ---- Edge terms (all lanes redundantly, branchless) ----
    const float TWO_PI = 6.2831853071795864769f;
    const float ex0 = ax,        ey0 = ay;
    const float ex1 = 1.0f - ax, ey1 = ay;
    const float ex2v = ay,       ey2 = ax;
    const float ex3 = 1.0f - ay, ey3 = ax;
    const float a10 = atan2_q1(ey0,        ex0);
    const float a20 = atan2_q1(1.0f - ey0, ex0);
    const float a11 = atan2_q1(ey1,        ex1);
    const float a21 = atan2_q1(1.0f - ey1, ex1);
    const float a12 = atan2_q1(ey2,        ex2v);
    const float a22 = atan2_q1(1.0f - ey2, ex2v);
    const float a13 = atan2_q1(ey3,        ex3);
    const float a23 = atan2_q1(1.0f - ey3, ex3);

    // ---- Per-lane weights for bins lane (rs1) and lane+32 (rs2) ----
    // acos(min(ex/rs,1)) = 0 when rs<=ex -> rs>ex guard is automatic.
    const float rs1 = (float)((lane +  1) * (5.0 / 50.0) * RMAX_D);
    const float rs2 = (float)((lane + 33) * (5.0 / 50.0) * RMAX_D);

    float w1, w2;
    {
        float ir = rcp_fast(rs1);
        float al0 = acos_poly(fminf(ex0  * ir, 1.0f));
        float al1 = acos_poly(fminf(ex1  * ir, 1.0f));
        float al2 = acos_poly(fminf(ex2v * ir, 1.0f));
        float al3 = acos_poly(fminf(ex3  * ir, 1.0f));
        float full = TWO_PI
            - (fminf(al0, a10) + fminf(al0, a20))
            - (fminf(al1, a11) + fminf(al1, a21))
            - (fminf(al2, a12) + fminf(al2, a22))
            - (fminf(al3, a13) + fminf(al3, a23));
        float per = fminf(fmaxf(full * (1.0f / TWO_PI), 0.0f), 1.0f);
        w1 = fminf(rcp_fast(fmaxf(per, 1e-9f)), 4.0f);
    }
    {
        float ir = rcp_fast(rs2);
        float al0 = acos_poly(fminf(ex0  * ir, 1.0f));
        float al1 = acos_poly(fminf(ex1  * ir, 1.0f));
        float al2 = acos_poly(fminf(ex2v * ir, 1.0f));
        float al3 = acos_poly(fminf(ex3  * ir, 1.0f));
        float full = TWO_PI
            - (fminf(al0, a10) + fminf(al0, a20))
            - (fminf(al1, a11) + fminf(al1, a21))
            - (fminf(al2, a12) + fminf(al2, a22))
            - (fminf(al3, a13) + fminf(al3, a23));
        float per = fminf(fmaxf(full * (1.0f / TWO_PI), 0.0f), 1.0f);
        w2 = fminf(rcp_fast(fmaxf(per, 1e-9f)), 4.0f);
        if (lane >= NBINS - 32) w2 = 0.0f;   // dead bins contribute 0
    }

    // ---- exp2 coefficients: exp(-16 (zb-u)^2) = ex2(c0 + c1 u + c2 u^2) ----
    const float L2E = 1.4426950408889634f;
    const float c2  = -16.0f * L2E;
    const float zb1 = 0.1f * (float)(lane + 1);
    const float zb2 = zb1 + 3.2f;
    const float c1a = 32.0f * zb1 * L2E;
    const float c0a = -16.0f * zb1 * zb1 * L2E;
    const float c1b = 32.0f * zb2 * L2E;
    const float c0b = -16.0f * zb2 * zb2 * L2E;

    const int   same = *scp;
    const float cut2 = (5.0f + ZC) * (5.0f + ZC);   // u-units

    __syncthreads();   // sbx/sby + sacc ready

    // ---- Phase A: ballot + popc-prefix compaction into warp queue ----
    int cnt = 0;
    const unsigned lt_mask = (1u << lane) - 1u;
#pragma unroll 4
    for (int jt = 0; jt < JITERS; jt++) {
        int   jl = jt * 32 + lane;
        float dx = axs - sbx[jl];
        float dy = ays - sby[jl];
        float d2 = fmaf(dx, dx, dy * dy);
        bool pred = (d2 < cut2) && !(same && i == (j0 + jl));
        unsigned mask = __ballot_sync(0xFFFFFFFFu, pred);
        if (pred) {
            int slot = cnt + __popc(mask & lt_mask);
            wq[slot] = sqrtf(d2);             // u = d/RMAX directly
        }
        cnt += __popc(mask);
    }
    __syncwarp();

    // ---- Phase B: counted drain, 2-way unroll, branchless both halves ----
    float acc1 = 0.0f, acc2 = 0.0f;
    int e = 0;
    for (; e + 1 < cnt; e += 2) {
        float uA  = wq[e];                    // LDS broadcast
        float uB  = wq[e + 1];
        float uA2 = uA * uA;
        float uB2 = uB * uB;
        float gA1 = ex2_fast(fmaf(c2, uA2, fmaf(c1a, uA, c0a)));
        float gB1 = ex2_fast(fmaf(c2, uB2, fmaf(c1a, uB, c0a)));
        float gA2 = ex2_fast(fmaf(c2, uA2, fmaf(c1b, uA, c0b)));
        float gB2 = ex2_fast(fmaf(c2, uB2, fmaf(c1b, uB, c0b)));
        acc1 = fmaf(gA1, w1, acc1);
        acc1 = fmaf(gB1, w1, acc1);
        acc2 = fmaf(gA2, w2, acc2);
        acc2 = fmaf(gB2, w2, acc2);
    }
    if (e < cnt) {
        float u  = wq[e];
        float u2 = u * u;
        acc1 = fmaf(ex2_fast(fmaf(c2, u2, fmaf(c1a, u, c0a))), w1, acc1);
        acc2 = fmaf(ex2_fast(fmaf(c2, u2, fmaf(c1b, u, c0b))), w2, acc2);
    }

    // ---- Block reduction -> global ----
    atomicAdd(&sacc[lane], acc1);
    if (lane < NBINS - 32) atomicAdd(&sacc[lane + 32], acc2);
    __syncthreads();
    if (tid < NBINS) atomicAdd(&g_acc[tid], sacc[tid]);

    // ---- Last block finalizes ----
    __threadfence();
    if (tid == 0) {
        int v = atomicAdd(&g_done, 1);
        is_last = (v == NBLK - 1);
    }
    __syncthreads();
    if (is_last) {
        if (tid < NBINS) {
            int b = tid;
            double rs_d  = (b + 1) * (5.0 / 50.0) * RMAX_D;
            double inner = fmax(0.0, rs_d - 0.5 * RMAX_D);
            double outer = rs_d + 0.5 * RMAX_D;
            float  area  = (float)(M_PI * (outer * outer - inner * inner));
            const float GF = (float)(1.0 / (sqrt(M_PI) * 0.25));

            float s   = g_acc[b] * GF;
            float pcf = s / 1536.0f / (area * 1536.0f);

            out[2 * b]     = (float)rs_d / (float)RMAX_D;
            out[2 * b + 1] = pcf;

            g_acc[b] = 0.0f;          // reset for next graph replay
        }
        if (tid == 0) g_done = 0;
    }
}

// ---------------------------------------------------------------------------
extern "C" void kernel_launch(void* const* d_in, const int* in_sizes, int n_in,
                              void* d_out, int out_size)
{
    const float* A  = (const float*)d_in[0];   // disks_a [1536,3]
    const float* B  = (const float*)d_in[1];   // disks_b [1536,3]
    const int*   sc = (const int*)d_in[2];     // same_category scalar
    float* out = (float*)d_out;

    pcf_kernel<<<NBLK, NTHR>>>(A, B, sc, out);
}

// round 12
// speedup vs baseline: 1.0172x; 1.0172x over previous
#include <cuda_runtime.h>
#include <math.h>

// ---------------------------------------------------------------------------
// PrettyPCF, R12 = R10 skeleton with:
//  * JSPLIT=2 (384 blocks) -> weight prologue duplicated 2x instead of 4x.
//  * atan2 edge terms computed by lanes 0-7, shfl-broadcast (8 MUFU+~100
//    instr saved per warp-task).
//  * Drain with warp-UNIFORM half-skip: u<4.4 -> low bins live (P=.50),
//    u>2.1 -> high bins live (P=.885); cuts EX2 count ~30% (MUFU floor).
//  * Everything else proven: scaled coords, rcp.approx, ballot+popc queue,
//    per-lane register weights, done-counter finalize.
// ---------------------------------------------------------------------------

#define NPTS   1536
#define NBINS  50
#define WPB    8                   // warps (== i-points) per block
#define NTHR   (WPB * 32)          // 256
#define ITILES (NPTS / WPB)        // 192
#define JSPLIT 2
#define JLEN   (NPTS / JSPLIT)     // 768
#define JITERS (JLEN / 32)         // 24
#define NBLK   (ITILES * JSPLIT)   // 384
#define QW     JLEN                // provable worst-case queue bound
#define ZC     1.2f

#define RMAX_D (2.0 * sqrt(1.0 / (2.0 * sqrt(3.0) * 1536.0)))

__device__ float g_acc[NBINS];   // zero-init at load; reset by last block
__device__ int   g_done;

__device__ __forceinline__ float ex2_fast(float x) {
    float y;
    asm("ex2.approx.ftz.f32 %0, %1;" : "=f"(y) : "f"(x));
    return y;
}
__device__ __forceinline__ float rcp_fast(float x) {
    float y;
    asm("rcp.approx.ftz.f32 %0, %1;" : "=f"(y) : "f"(x));
    return y;
}

// acos(x), x in [0,1]; abs err < 6.7e-5 (A&S 4.4.45). acos(1) = 0 exactly.
__device__ __forceinline__ float acos_poly(float x) {
    float p = fmaf(x, fmaf(x, fmaf(x, -0.0187293f, 0.0742610f),
                               -0.2121144f), 1.5707288f);
    return sqrtf(1.0f - x) * p;
}

// atan(r), r in [0,1]; minimax odd poly, abs err ~1e-6.
__device__ __forceinline__ float atan_poly(float r) {
    float r2 = r * r;
    float p = fmaf(r2, fmaf(r2, fmaf(r2, fmaf(r2, fmaf(r2,
              -0.0117212f, 0.05265332f), -0.11643287f),
               0.19354346f), -0.33262347f), 0.99997726f);
    return r * p;
}

// atan2(y, x) for x,y >= 0 (first quadrant), branchless, rcp-based.
__device__ __forceinline__ float atan2_q1(float y, float x) {
    float mn = fminf(x, y);
    float mx = fmaxf(x, y);
    float r  = mn * rcp_fast(fmaxf(mx, 1e-20f));
    float a  = atan_poly(r);
    return (y > x) ? (1.5707963268f - a) : a;
}

__global__ __launch_bounds__(NTHR)
void pcf_kernel(const float* __restrict__ A, const float* __restrict__ B,
                const int* __restrict__ scp, float* __restrict__ out)
{
    __shared__ float sbx[JLEN];          // B x, pre-scaled by 1/RMAX
    __shared__ float sby[JLEN];          // B y, pre-scaled
    __shared__ float swq[WPB * QW];      // per-warp survivor u's
    __shared__ float sacc[NBINS];
    __shared__ int   is_last;

    const int tid   = threadIdx.x;
    const int lane  = tid & 31;
    const int wid   = tid >> 5;
    const int itile = blockIdx.x % ITILES;
    const int jsp   = blockIdx.x / ITILES;
    const int i0    = itile * WPB;
    const int j0    = jsp * JLEN;
    const int i     = i0 + wid;          // this warp's i-point
    float* wq = &swq[wid * QW];

    const float invR = (float)(1.0 / RMAX_D);

    // ---- Stage this block's B slice (scaled to u-units) ----
    for (int t = tid; t < JLEN; t += NTHR) {
        sbx[t] = B[3 * (j0 + t)]     * invR;
        sby[t] = B[3 * (j0 + t) + 1] * invR;
    }
    if (tid < NBINS) sacc[tid] = 0.0f;

    // ---- This warp's i coords ----
    const float ax = A[3 * i];
    const float ay = A[3 * i + 1];
    const float axs = ax * invR;
    const float ays = ay * invR;

    const float TWO_PI = 6.2831853071795864769f;
    const float ex0 = ax,  ex1 = 1.0f - ax;
    const float ex2v = ay, ex3 = 1.0f - ay;

    // ---- atan2 edge terms: lanes 0-7 compute one each, shfl-broadcast ----
    float aval = 0.0f;
    if (lane < 8) {
        int e     = lane >> 1;
        int which = lane & 1;
        float exk = (e == 0) ? ax : (e == 1) ? (1.0f - ax)
                  : (e == 2) ? ay : (1.0f - ay);
        float eyk = (e < 2) ? ay : ax;
        float yy  = which ? (1.0f - eyk) : eyk;
        aval = atan2_q1(yy, exk);
    }
    const float a10 = __shfl_sync(0xFFFFFFFFu, aval, 0);
    const float a20 = __shfl_sync(0xFFFFFFFFu, aval, 1);
    const float a11 = __shfl_sync(0xFFFFFFFFu, aval, 2);
    const float a21 = __shfl_sync(0xFFFFFFFFu, aval, 3);
    const float a12 = __shfl_sync(0xFFFFFFFFu, aval, 4);
    const float a22 = __shfl_sync(0xFFFFFFFFu, aval, 5);
    const float a13 = __shfl_sync(0xFFFFFFFFu, aval, 6);
    const float a23 = __shfl_sync(0xFFFFFFFFu, aval, 7);

    // ---- Per-lane weights for bins lane (rs1) and lane+32 (rs2) ----
    // acos(min(ex/rs,1)) = 0 when rs<=ex -> rs>ex guard is automatic.
    const float rs1 = (float)((lane +  1) * (5.0 / 50.0) * RMAX_D);
    const float rs2 = (float)((lane + 33) * (5.0 / 50.0) * RMAX_D);

    float w1, w2;
    {
        float ir = rcp_fast(rs1);
        float al0 = acos_poly(fminf(ex0  * ir, 1.0f));
        float al1 = acos_poly(fminf(ex1  * ir, 1.0f));
        float al2 = acos_poly(fminf(ex2v * ir, 1.0f));
        float al3 = acos_poly(fminf(ex3  * ir, 1.0f));
        float full = TWO_PI
            - (fminf(al0, a10) + fminf(al0, a20))
            - (fminf(al1, a11) + fminf(al1, a21))
            - (fminf(al2, a12) + fminf(al2, a22))
            - (fminf(al3, a13) + fminf(al3, a23));
        float per = fminf(fmaxf(full * (1.0f / TWO_PI), 0.0f), 1.0f);
        w1 = fminf(rcp_fast(fmaxf(per, 1e-9f)), 4.0f);
    }
    {
        float ir = rcp_fast(rs2);
        float al0 = acos_poly(fminf(ex0  * ir, 1.0f));
        float al1 = acos_poly(fminf(ex1  * ir, 1.0f));
        float al2 = acos_poly(fminf(ex2v * ir, 1.0f));
        float al3 = acos_poly(fminf(ex3  * ir, 1.0f));
        float full = TWO_PI
            - (fminf(al0, a10) + fminf(al0, a20))
            - (fminf(al1, a11) + fminf(al1, a21))
            - (fminf(al2, a12) + fminf(al2, a22))
            - (fminf(al3, a13) + fminf(al3, a23));
        float per = fminf(fmaxf(full * (1.0f / TWO_PI), 0.0f), 1.0f);
        w2 = fminf(rcp_fast(fmaxf(per, 1e-9f)), 4.0f);
        if (lane >= NBINS - 32) w2 = 0.0f;   // dead bins contribute 0
    }

    // ---- exp2 coefficients: exp(-16 (zb-u)^2) = ex2(c0 + c1 u + c2 u^2) ----
    const float L2E = 1.4426950408889634f;
    const float c2  = -16.0f * L2E;
    const float zb1 = 0.1f * (float)(lane + 1);
    const float zb2 = zb1 + 3.2f;
    const float c1a = 32.0f * zb1 * L2E;
    const float c0a = -16.0f * zb1 * zb1 * L2E;
    const float c1b = 32.0f * zb2 * L2E;
    const float c0b = -16.0f * zb2 * zb2 * L2E;

    const int   same = *scp;
    const float cut2 = (5.0f + ZC) * (5.0f + ZC);   // u-units

    __syncthreads();   // sbx/sby + sacc ready

    // ---- Phase A: ballot + popc-prefix compaction into warp queue ----
    int cnt = 0;
    const unsigned lt_mask = (1u << lane) - 1u;
#pragma unroll 4
    for (int jt = 0; jt < JITERS; jt++) {
        int   jl = jt * 32 + lane;
        float dx = axs - sbx[jl];
        float dy = ays - sby[jl];
        float d2 = fmaf(dx, dx, dy * dy);
        bool pred = (d2 < cut2) && !(same && i == (j0 + jl));
        unsigned mask = __ballot_sync(0xFFFFFFFFu, pred);
        if (pred) {
            int slot = cnt + __popc(mask & lt_mask);
            wq[slot] = sqrtf(d2);             // u = d/RMAX directly
        }
        cnt += __popc(mask);
    }
    __syncwarp();

    // ---- Phase B: drain with warp-uniform half-skip ----
    // low half (bins 1..32, centers <= 3.2) live iff u < 3.2+ZC = 4.4
    // high half (bins 33..50, centers >= 3.3) live iff u > 3.3-ZC = 2.1
    float acc1 = 0.0f, acc2 = 0.0f;
    for (int e = 0; e < cnt; e++) {
        float u  = wq[e];                     // LDS broadcast, warp-uniform
        float u2 = u * u;
        if (u < 3.2f + ZC) {
            float arg = fmaf(c2, u2, fmaf(c1a, u, c0a));
            acc1 = fmaf(ex2_fast(arg), w1, acc1);
        }
        if (u > 3.3f - ZC) {
            float arg = fmaf(c2, u2, fmaf(c1b, u, c0b));
            acc2 = fmaf(ex2_fast(arg), w2, acc2);
        }
    }

    // ---- Block reduction -> global ----
    atomicAdd(&sacc[lane], acc1);
    if (lane < NBINS - 32) atomicAdd(&sacc[lane + 32], acc2);
    __syncthreads();
    if (tid < NBINS) atomicAdd(&g_acc[tid], sacc[tid]);

    // ---- Last block finalizes ----
    __threadfence();
    if (tid == 0) {
        int v = atomicAdd(&g_done, 1);
        is_last = (v == NBLK - 1);
    }
    __syncthreads();
    if (is_last) {
        if (tid < NBINS) {
            int b = tid;
            double rs_d  = (b + 1) * (5.0 / 50.0) * RMAX_D;
            double inner = fmax(0.0, rs_d - 0.5 * RMAX_D);
            double outer = rs_d + 0.5 * RMAX_D;
            float  area  = (float)(M_PI * (outer * outer - inner * inner));
            const float GF = (float)(1.0 / (sqrt(M_PI) * 0.25));

            float s   = g_acc[b] * GF;
            float pcf = s / 1536.0f / (area * 1536.0f);

            out[2 * b]     = (float)rs_d / (float)RMAX_D;
            out[2 * b + 1] = pcf;

            g_acc[b] = 0.0f;          // reset for next graph replay
        }
        if (tid == 0) g_done = 0;
    }
}

// ---------------------------------------------------------------------------
extern "C" void kernel_launch(void* const* d_in, const int* in_sizes, int n_in,
                              void* d_out, int out_size)
{
    const float* A  = (const float*)d_in[0];   // disks_a [1536,3]
    const float* B  = (const float*)d_in[1];   // disks_b [1536,3]
    const int*   sc = (const int*)d_in[2];     // same_category scalar
    float* out = (float*)d_out;

    pcf_kernel<<<NBLK, NTHR>>>(A, B, sc, out);
}